// round 4
// baseline (speedup 1.0000x reference)
#include <cuda_runtime.h>
#include <cstdint>

#define SEQ    512
#define BATCH  1024
#define NTAG   64
#define NEGINF -10000.0f
#define DEPTH  8

// g_E2[h*1024 + k*32 + l] = packed f32x2 ( exp(T[l+32h][2k]), exp(T[l+32h][2k+1]) )
__device__ __align__(16) unsigned long long g_E2[2 * 32 * 32];
__device__ int g_len[BATCH];

__device__ __forceinline__ float ex2f_(float x) {
    float y; asm("ex2.approx.ftz.f32 %0, %1;" : "=f"(y) : "f"(x)); return y;
}
__device__ __forceinline__ float lg2f_(float x) {
    float y; asm("lg2.approx.ftz.f32 %0, %1;" : "=f"(y) : "f"(x)); return y;
}
__device__ __forceinline__ unsigned long long fma2_(unsigned long long a,
                                                    unsigned long long b,
                                                    unsigned long long c) {
    unsigned long long d;
    asm("fma.rn.f32x2 %0, %1, %2, %3;" : "=l"(d) : "l"(a), "l"(b), "l"(c));
    return d;
}
__device__ __forceinline__ unsigned long long add2_(unsigned long long a,
                                                    unsigned long long b) {
    unsigned long long d;
    asm("add.rn.f32x2 %0, %1, %2;" : "=l"(d) : "l"(a), "l"(b));
    return d;
}
__device__ __forceinline__ void unpack_(unsigned long long v, float& x, float& y) {
    asm("mov.b64 {%0, %1}, %2;" : "=f"(x), "=f"(y) : "l"(v));
}
__device__ __forceinline__ float wmax_(float v) {
#pragma unroll
    for (int d = 16; d; d >>= 1)
        v = fmaxf(v, __shfl_xor_sync(0xffffffffu, v, d));
    return v;
}
__device__ __forceinline__ uint32_t smem_u32_(const void* p) {
    uint32_t a;
    asm("{ .reg .u64 t; cvta.to.shared.u64 t, %1; cvt.u32.u64 %0, t; }"
        : "=r"(a) : "l"(p));
    return a;
}
__device__ __forceinline__ void cpa8_(uint32_t dst, const float* src) {
    asm volatile("cp.async.ca.shared.global [%0], [%1], 8;" :: "r"(dst), "l"(src));
}
__device__ __forceinline__ void cpa_commit_() {
    asm volatile("cp.async.commit_group;" ::: "memory");
}
__device__ __forceinline__ void cpa_wait_() {
    asm volatile("cp.async.wait_group %0;" :: "n"(DEPTH - 1) : "memory");
}

// blocks 0..31: len[b] = sum of monotone mask column; blocks 32..39: E table.
__global__ void crf_prep(const float* __restrict__ trans,
                         const float* __restrict__ mask) {
    if (blockIdx.x < 32) {
        const int l = threadIdx.x & 31, c = threadIdx.x >> 5;
        const int b = blockIdx.x * 32 + l;
        float s = 0.0f;
#pragma unroll
        for (int i = 0; i < 64; ++i)
            s += mask[(size_t)(c * 64 + i) * BATCH + b];
        __shared__ float red[8][32];
        red[c][l] = s;
        __syncthreads();
        if (c == 0) {
            float t = 0.0f;
#pragma unroll
            for (int k = 0; k < 8; ++k) t += red[k][l];
            g_len[b] = (int)(t + 0.5f);
        }
    } else {
        const int t = (blockIdx.x - 32) * 256 + threadIdx.x;
        const int l = t & 31, k = (t >> 5) & 31, h = t >> 10;
        const int j = l + 32 * h;
        const float e0 = __expf(trans[j * NTAG + 2 * k]);   // exp(-1e4) -> 0
        const float e1 = __expf(trans[j * NTAG + 2 * k + 1]);
        unsigned long long u;
        asm("mov.b64 %0, {%1, %2};" : "=l"(u) : "f"(e0), "f"(e1));
        g_E2[h * 1024 + k * 32 + l] = u;
    }
}

// One warp = one CTA = TWO batches (b, b+512). The 128-register E table is
// shared; the second recurrence provides the ILP that hides the ~170-cycle
// per-step serial chain exposed in R3.
__global__ void __launch_bounds__(32)
crf_main(const float* __restrict__ feats,
         const float* __restrict__ trans,
         float* __restrict__ out) {
    const int lane = threadIdx.x;
    const int bA   = blockIdx.x;
    const int bB   = blockIdx.x + 512;

    __shared__ __align__(16) float ring[DEPTH][2][NTAG];  // 4 KB
    __shared__ __align__(16) float pbuf[2][2][NTAG];      // [phase][batch][tag]

    unsigned long long EA[32], EB[32];
#pragma unroll
    for (int k = 0; k < 32; ++k) {
        EA[k] = g_E2[k * 32 + lane];
        EB[k] = g_E2[1024 + k * 32 + lane];
    }

    const float LN2 = 0.6931471805599453f;
    const float L2E = 1.4426950408889634f;

    // Kv = log(max_j sum_i E[j,i]) + margin, from resident E regs
    float Kv;
    {
        unsigned long long sa = 0ull, sb = 0ull;
#pragma unroll
        for (int k = 0; k < 32; ++k) { sa = add2_(sa, EA[k]); sb = add2_(sb, EB[k]); }
        float a0, a1, b0, b1;
        unpack_(sa, a0, a1); unpack_(sb, b0, b1);
        const float rs = wmax_(fmaxf(a0 + a1, b0 + b1));
        Kv = fmaf(lg2f_(fmaxf(rs, 1e-30f)), LN2, 1.0f);
    }

    const float t_lo = trans[1 * NTAG + lane];       // END row
    const float t_hi = trans[1 * NTAG + 32 + lane];
    const int lenA = g_len[bA];
    const int lenB = g_len[bB];
    const int lm   = lenA > lenB ? lenA : lenB;

    float aA_lo = (lane == 0) ? 0.0f : NEGINF;       // START_IDX = 0
    float aA_hi = NEGINF;
    float aB_lo = aA_lo;
    float aB_hi = NEGINF;

    const float* fA = feats + (size_t)bA * NTAG;     // step s at +s*65536
    const float* fB = feats + (size_t)bB * NTAG;
    const uint32_t ring_u = smem_u32_(&ring[0][0][0]);
    const uint32_t dA = ring_u + lane * 8;           // batch A half of slot
    const uint32_t dB = ring_u + 256 + lane * 8;     // batch B half (+64 floats)

    // prologue: slots 0..DEPTH-2 (each group = both batches' 8B/lane)
#pragma unroll
    for (int t = 0; t < DEPTH - 1; ++t) {
        cpa8_(dA + (t << 9), fA + ((size_t)t << 16) + lane * 2);
        cpa8_(dB + (t << 9), fB + ((size_t)t << 16) + lane * 2);
        cpa_commit_();
    }

    float muA = 0.0f, MA = 0.0f;   // mu_c and M_{s-1} per batch
    float muB = 0.0f, MB = 0.0f;

#pragma unroll 1
    for (int s = 0; s < lm; ++s) {
        const int ph = s & 1;

        // p = exp(alpha - mu); mu known since last iteration (off chain)
        pbuf[ph][0][lane]      = ex2f_(fmaf(aA_lo, L2E, -muA * L2E));
        pbuf[ph][0][lane + 32] = ex2f_(fmaf(aA_hi, L2E, -muA * L2E));
        pbuf[ph][1][lane]      = ex2f_(fmaf(aB_lo, L2E, -muB * L2E));
        pbuf[ph][1][lane + 32] = ex2f_(fmaf(aB_hi, L2E, -muB * L2E));

        // stream slot s+DEPTH-1 (clamped; dup tail writes are byte-identical)
        int sp = s + DEPTH - 1;
        if (sp > SEQ - 1) sp = SEQ - 1;
        const uint32_t so = (uint32_t)(sp & (DEPTH - 1)) << 9;
        cpa8_(dA + so, fA + ((size_t)sp << 16) + lane * 2);
        cpa8_(dB + so, fB + ((size_t)sp << 16) + lane * 2);
        cpa_commit_();
        cpa_wait_();
        __syncwarp();

        const int rs = s & (DEPTH - 1);
        const float fA_lo = ring[rs][0][lane];
        const float fA_hi = ring[rs][0][lane + 32];
        const float fB_lo = ring[rs][1][lane];
        const float fB_hi = ring[rs][1][lane + 32];

        // S_j = sum_i E[j,i] p_i for both batches: 32 LDS.128 + 128 FFMA2
        const ulonglong2* pA = reinterpret_cast<const ulonglong2*>(&pbuf[ph][0][0]);
        const ulonglong2* pB = reinterpret_cast<const ulonglong2*>(&pbuf[ph][1][0]);
        unsigned long long xA0 = 0ull, xA1 = 0ull, xA2 = 0ull, xA3 = 0ull;
        unsigned long long xB0 = 0ull, xB1 = 0ull, xB2 = 0ull, xB3 = 0ull;
#pragma unroll
        for (int k = 0; k < 16; ++k) {
            const ulonglong2 qa = pA[k];
            const ulonglong2 qb = pB[k];
            xA0 = fma2_(EA[2 * k],     qa.x, xA0);
            xA1 = fma2_(EA[2 * k + 1], qa.y, xA1);
            xA2 = fma2_(EB[2 * k],     qa.x, xA2);
            xA3 = fma2_(EB[2 * k + 1], qa.y, xA3);
            xB0 = fma2_(EA[2 * k],     qb.x, xB0);
            xB1 = fma2_(EA[2 * k + 1], qb.y, xB1);
            xB2 = fma2_(EB[2 * k],     qb.x, xB2);
            xB3 = fma2_(EB[2 * k + 1], qb.y, xB3);
        }
        float u0, u1, v0, v1;
        unpack_(add2_(xA0, xA1), u0, u1);
        unpack_(add2_(xA2, xA3), v0, v1);
        const float SA_lo = u0 + u1, SA_hi = v0 + v1;
        unpack_(add2_(xB0, xB1), u0, u1);
        unpack_(add2_(xB2, xB3), v0, v1);
        const float SB_lo = u0 + u1, SB_hi = v0 + v1;

        // alpha' = mu + feat + log S (exact for any mu; floor kills the
        // all-zero START row's log(0)); freeze once past this batch's len
        const float nA_lo = fmaf(lg2f_(fmaxf(SA_lo, 1e-37f)), LN2, muA + fA_lo);
        const float nA_hi = fmaf(lg2f_(fmaxf(SA_hi, 1e-37f)), LN2, muA + fA_hi);
        const float nB_lo = fmaf(lg2f_(fmaxf(SB_lo, 1e-37f)), LN2, muB + fB_lo);
        const float nB_hi = fmaf(lg2f_(fmaxf(SB_hi, 1e-37f)), LN2, muB + fB_hi);
        const bool uA = s < lenA;
        const bool uB = s < lenB;
        aA_lo = uA ? nA_lo : aA_lo;
        aA_hi = uA ? nA_hi : aA_hi;
        aB_lo = uB ? nB_lo : aB_lo;
        aB_hi = uB ? nB_hi : aB_hi;

        // normalizer pipeline (off critical path):
        // mu_{s+1} = M_{s-1} + max(wmax(f_s)+K, 0);  M <- wmax(alpha_s)
        const float iA = fmaxf(wmax_(fmaxf(fA_lo, fA_hi)) + Kv, 0.0f);
        const float iB = fmaxf(wmax_(fmaxf(fB_lo, fB_hi)) + Kv, 0.0f);
        muA = MA + iA;
        muB = MB + iB;
        MA = wmax_(fmaxf(aA_lo, aA_hi));
        MB = wmax_(fmaxf(aB_lo, aB_hi));
    }

    // out[b] = LSE_j( alpha[j] + T[END][j] ), both batches
    {
        const float x_lo = aA_lo + t_lo, x_hi = aA_hi + t_hi;
        const float m = wmax_(fmaxf(x_lo, x_hi));
        float ss = ex2f_(fmaf(x_lo, L2E, -m * L2E)) +
                   ex2f_(fmaf(x_hi, L2E, -m * L2E));
#pragma unroll
        for (int d = 16; d; d >>= 1)
            ss += __shfl_xor_sync(0xffffffffu, ss, d);
        if (lane == 0) out[bA] = fmaf(lg2f_(ss), LN2, m);
    }
    {
        const float x_lo = aB_lo + t_lo, x_hi = aB_hi + t_hi;
        const float m = wmax_(fmaxf(x_lo, x_hi));
        float ss = ex2f_(fmaf(x_lo, L2E, -m * L2E)) +
                   ex2f_(fmaf(x_hi, L2E, -m * L2E));
#pragma unroll
        for (int d = 16; d; d >>= 1)
            ss += __shfl_xor_sync(0xffffffffu, ss, d);
        if (lane == 0) out[bB] = fmaf(lg2f_(ss), LN2, m);
    }
}

extern "C" void kernel_launch(void* const* d_in, const int* in_sizes, int n_in,
                              void* d_out, int out_size) {
    const float* feats = nullptr;
    const float* maskp = nullptr;
    const float* trans = nullptr;
    for (int i = 0; i < n_in; ++i) {
        if (in_sizes[i] == SEQ * BATCH * NTAG)      feats = (const float*)d_in[i];
        else if (in_sizes[i] == SEQ * BATCH)        maskp = (const float*)d_in[i];
        else if (in_sizes[i] == NTAG * NTAG)        trans = (const float*)d_in[i];
    }
    crf_prep<<<40, 256>>>(trans, maskp);
    crf_main<<<BATCH / 2, 32>>>(feats, trans, (float*)d_out);
}